// round 2
// baseline (speedup 1.0000x reference)
#include <cuda_runtime.h>
#include <cuda_bf16.h>
#include <cstdint>

#define N 4096
#define DF 64

// Scratch (allocation-free rule: __device__ globals)
__device__ float g_D[(size_t)N * N];   // 64 MB distance matrix, diagonal = +inf
__device__ float g_sq[N];              // squared norms

__device__ __forceinline__ float finf() { return __int_as_float(0x7f800000); }

// ---------------------------------------------------------------------------
// Kernel 0: squared norms
// ---------------------------------------------------------------------------
__global__ void sq_kernel(const float* __restrict__ x) {
    int i = blockIdx.x * blockDim.x + threadIdx.x;
    if (i >= N) return;
    const float4* xi = (const float4*)(x + (size_t)i * DF);
    float s = 0.f;
#pragma unroll
    for (int k = 0; k < DF / 4; k++) {
        float4 v = xi[k];
        s += v.x * v.x + v.y * v.y + v.z * v.z + v.w * v.w;
    }
    g_sq[i] = s;
}

// ---------------------------------------------------------------------------
// Kernel 1: distance matrix, 64x64 tiles, 256 threads, 4x4 per thread.
// Shared layout transposed [k][row] with pad 68 so inner loop uses float4 LDS.
// ---------------------------------------------------------------------------
__global__ __launch_bounds__(256) void dist_kernel(const float* __restrict__ x) {
    __shared__ __align__(16) float sA[DF * 68];
    __shared__ __align__(16) float sB[DF * 68];

    const int t    = threadIdx.x;
    const int lrow = t >> 2;      // 0..63
    const int q    = t & 3;       // 0..3 (quarter of the 64-float row)
    const int i0   = blockIdx.y * 64;
    const int j0   = blockIdx.x * 64;

    // Load A tile (rows i0..i0+63) and B tile (rows j0..j0+63), transposed.
    {
        const float4* xa = (const float4*)(x + (size_t)(i0 + lrow) * DF) + q * 4;
        const float4* xb = (const float4*)(x + (size_t)(j0 + lrow) * DF) + q * 4;
#pragma unroll
        for (int u = 0; u < 4; u++) {
            float4 va = xa[u];
            float4 vb = xb[u];
            int k0 = q * 16 + u * 4;
            sA[(k0 + 0) * 68 + lrow] = va.x;
            sA[(k0 + 1) * 68 + lrow] = va.y;
            sA[(k0 + 2) * 68 + lrow] = va.z;
            sA[(k0 + 3) * 68 + lrow] = va.w;
            sB[(k0 + 0) * 68 + lrow] = vb.x;
            sB[(k0 + 1) * 68 + lrow] = vb.y;
            sB[(k0 + 2) * 68 + lrow] = vb.z;
            sB[(k0 + 3) * 68 + lrow] = vb.w;
        }
    }
    __syncthreads();

    const int tx = t & 15;   // col group
    const int ty = t >> 4;   // row group

    float acc[4][4];
#pragma unroll
    for (int r = 0; r < 4; r++)
#pragma unroll
        for (int c = 0; c < 4; c++) acc[r][c] = 0.f;

#pragma unroll 8
    for (int k = 0; k < DF; k++) {
        float4 a = *(const float4*)&sA[k * 68 + ty * 4];
        float4 b = *(const float4*)&sB[k * 68 + tx * 4];
        float av[4] = {a.x, a.y, a.z, a.w};
        float bv[4] = {b.x, b.y, b.z, b.w};
#pragma unroll
        for (int r = 0; r < 4; r++)
#pragma unroll
            for (int c = 0; c < 4; c++) acc[r][c] = fmaf(av[r], bv[c], acc[r][c]);
    }

    float sqI[4], sqJ[4];
#pragma unroll
    for (int r = 0; r < 4; r++) sqI[r] = g_sq[i0 + ty * 4 + r];
#pragma unroll
    for (int c = 0; c < 4; c++) sqJ[c] = g_sq[j0 + tx * 4 + c];

#pragma unroll
    for (int r = 0; r < 4; r++) {
        int gi = i0 + ty * 4 + r;
        float4 o;
        float ov[4];
#pragma unroll
        for (int c = 0; c < 4; c++) {
            int gj = j0 + tx * 4 + c;
            float d2 = sqI[r] + sqJ[c] - 2.f * acc[r][c];
            float d  = sqrtf(fmaxf(d2, 1e-12f));
            ov[c] = (gi == gj) ? finf() : d;
        }
        o.x = ov[0]; o.y = ov[1]; o.z = ov[2]; o.w = ov[3];
        *(float4*)(g_D + (size_t)gi * N + j0 + tx * 4) = o;
    }
}

// ---------------------------------------------------------------------------
// Kernel 2: Prim scan. Single CTA, 1024 threads, 4 elems/thread.
// mind in shared; sentinel -1.0 marks in-tree (fminf preserves it).
// Argmin key = (float_bits << 32) | index  -> first-occurrence on ties.
// ---------------------------------------------------------------------------
__global__ __launch_bounds__(1024, 1) void prim_kernel(float* __restrict__ out) {
    __shared__ __align__(16) float s_mind[N];
    __shared__ unsigned long long s_warp[32];
    __shared__ int s_j;

    const int tid = threadIdx.x;

    // init: everything +inf, vertex 0 in tree
#pragma unroll
    for (int r = 0; r < 4; r++) s_mind[tid + r * 1024] = finf();
    if (tid == 0) { s_mind[0] = -1.0f; s_j = 0; }
    __syncthreads();

    float4* mind4 = (float4*)s_mind;

    for (int step = 0; step < N - 1; step++) {
        const int j = s_j;
        float4 d = __ldcg((const float4*)(g_D + (size_t)j * N) + tid);
        float4 m = mind4[tid];
        float4 c;
        c.x = fminf(m.x, d.x);
        c.y = fminf(m.y, d.y);
        c.z = fminf(m.z, d.z);
        c.w = fminf(m.w, d.w);
        mind4[tid] = c;

        // masked local argmin (ascending index, strict < => first occurrence)
        float cv[4] = {c.x, c.y, c.z, c.w};
        float best = finf();
        int   bi   = tid * 4;
#pragma unroll
        for (int e = 0; e < 4; e++) {
            float v = (cv[e] < 0.f) ? finf() : cv[e];
            if (v < best) { best = v; bi = tid * 4 + e; }
        }
        unsigned long long key =
            ((unsigned long long)__float_as_uint(best) << 32) | (unsigned)bi;

#pragma unroll
        for (int o = 16; o; o >>= 1) {
            unsigned long long k2 = __shfl_xor_sync(0xffffffffu, key, o);
            if (k2 < key) key = k2;
        }
        if ((tid & 31) == 0) s_warp[tid >> 5] = key;
        __syncthreads();

        if (tid < 32) {
            unsigned long long k2 = s_warp[tid];
#pragma unroll
            for (int o = 16; o; o >>= 1) {
                unsigned long long k3 = __shfl_xor_sync(0xffffffffu, k2, o);
                if (k3 < k2) k2 = k3;
            }
            if (tid == 0) {
                int   jn    = (int)(k2 & 0xffffffffu);
                float death = __uint_as_float((unsigned)(k2 >> 32));
                *(float2*)(out + 2 * step) = make_float2(0.0f, death);
                s_mind[jn] = -1.0f;   // join tree
                s_j = jn;
            }
        }
        __syncthreads();
    }
}

// ---------------------------------------------------------------------------
extern "C" void kernel_launch(void* const* d_in, const int* in_sizes, int n_in,
                              void* d_out, int out_size) {
    const float* x   = (const float*)d_in[0];
    float*       out = (float*)d_out;

    sq_kernel<<<(N + 255) / 256, 256>>>(x);
    dim3 grid(N / 64, N / 64);
    dist_kernel<<<grid, 256>>>(x);
    prim_kernel<<<1, 1024>>>(out);
}

// round 5
// speedup vs baseline: 1.1899x; 1.1899x over previous
#include <cuda_runtime.h>
#include <cuda_bf16.h>
#include <cstdint>

#define N 4096
#define DF 64

// Scratch (allocation-free rule: __device__ globals)
__device__ float g_D[(size_t)N * N];   // 64 MB distance matrix, diagonal = +inf
__device__ float g_sq[N];              // squared norms

__device__ __forceinline__ float finf() { return __int_as_float(0x7f800000); }

// ---------------------------------------------------------------------------
// Kernel 0: squared norms
// ---------------------------------------------------------------------------
__global__ void sq_kernel(const float* __restrict__ x) {
    int i = blockIdx.x * blockDim.x + threadIdx.x;
    if (i >= N) return;
    const float4* xi = (const float4*)(x + (size_t)i * DF);
    float s = 0.f;
#pragma unroll
    for (int k = 0; k < DF / 4; k++) {
        float4 v = xi[k];
        s += v.x * v.x + v.y * v.y + v.z * v.z + v.w * v.w;
    }
    g_sq[i] = s;
}

// ---------------------------------------------------------------------------
// Kernel 1: distance matrix, 64x64 tiles, 256 threads, 4x4 per thread.
// ---------------------------------------------------------------------------
__global__ __launch_bounds__(256) void dist_kernel(const float* __restrict__ x) {
    __shared__ __align__(16) float sA[DF * 68];
    __shared__ __align__(16) float sB[DF * 68];

    const int t    = threadIdx.x;
    const int lrow = t >> 2;      // 0..63
    const int q    = t & 3;       // 0..3
    const int i0   = blockIdx.y * 64;
    const int j0   = blockIdx.x * 64;

    {
        const float4* xa = (const float4*)(x + (size_t)(i0 + lrow) * DF) + q * 4;
        const float4* xb = (const float4*)(x + (size_t)(j0 + lrow) * DF) + q * 4;
#pragma unroll
        for (int u = 0; u < 4; u++) {
            float4 va = xa[u];
            float4 vb = xb[u];
            int k0 = q * 16 + u * 4;
            sA[(k0 + 0) * 68 + lrow] = va.x;
            sA[(k0 + 1) * 68 + lrow] = va.y;
            sA[(k0 + 2) * 68 + lrow] = va.z;
            sA[(k0 + 3) * 68 + lrow] = va.w;
            sB[(k0 + 0) * 68 + lrow] = vb.x;
            sB[(k0 + 1) * 68 + lrow] = vb.y;
            sB[(k0 + 2) * 68 + lrow] = vb.z;
            sB[(k0 + 3) * 68 + lrow] = vb.w;
        }
    }
    __syncthreads();

    const int tx = t & 15;
    const int ty = t >> 4;

    float acc[4][4];
#pragma unroll
    for (int r = 0; r < 4; r++)
#pragma unroll
        for (int c = 0; c < 4; c++) acc[r][c] = 0.f;

#pragma unroll 8
    for (int k = 0; k < DF; k++) {
        float4 a = *(const float4*)&sA[k * 68 + ty * 4];
        float4 b = *(const float4*)&sB[k * 68 + tx * 4];
        float av[4] = {a.x, a.y, a.z, a.w};
        float bv[4] = {b.x, b.y, b.z, b.w};
#pragma unroll
        for (int r = 0; r < 4; r++)
#pragma unroll
            for (int c = 0; c < 4; c++) acc[r][c] = fmaf(av[r], bv[c], acc[r][c]);
    }

    float sqI[4], sqJ[4];
#pragma unroll
    for (int r = 0; r < 4; r++) sqI[r] = g_sq[i0 + ty * 4 + r];
#pragma unroll
    for (int c = 0; c < 4; c++) sqJ[c] = g_sq[j0 + tx * 4 + c];

#pragma unroll
    for (int r = 0; r < 4; r++) {
        int gi = i0 + ty * 4 + r;
        float4 o;
        float ov[4];
#pragma unroll
        for (int c = 0; c < 4; c++) {
            int gj = j0 + tx * 4 + c;
            float d2 = sqI[r] + sqJ[c] - 2.f * acc[r][c];
            float d  = sqrtf(fmaxf(d2, 1e-12f));
            ov[c] = (gi == gj) ? finf() : d;
        }
        o.x = ov[0]; o.y = ov[1]; o.z = ov[2]; o.w = ov[3];
        *(float4*)(g_D + (size_t)gi * N + j0 + tx * 4) = o;
    }
}

// ---------------------------------------------------------------------------
// Kernel 2: Prim scan. Single CTA, 512 threads, 8 elems/thread IN REGISTERS.
//  - sentinel -1.0 marks in-tree (fminf preserves it; masked to +inf for argmin)
//  - stage1: warp-wide redux.min on value bits + ballot/ffs/shfl for index
//            (lane order == index order -> first-occurrence tiebreak)
//  - stage2: every warp redundantly reduces the 16 per-warp keys, so all
//            threads learn j without a second barrier (double-buffered s_warp)
// ---------------------------------------------------------------------------
__global__ __launch_bounds__(512, 1) void prim_kernel(float* __restrict__ out) {
    __shared__ unsigned long long s_warp[2][16];

    const int tid  = threadIdx.x;
    const int lane = tid & 31;
    const int wid  = tid >> 5;

    float m[8];
#pragma unroll
    for (int e = 0; e < 8; e++) m[e] = finf();
    if (tid == 0) m[0] = -1.0f;   // vertex 0 starts in the tree

    int j   = 0;
    int par = 0;

    for (int step = 0; step < N - 1; step++) {
        const float4* row = (const float4*)(g_D + (size_t)j * N);
        float4 a = __ldcg(row + tid * 2);
        float4 b = __ldcg(row + tid * 2 + 1);
        float dv[8] = {a.x, a.y, a.z, a.w, b.x, b.y, b.z, b.w};

        unsigned bestv = 0x7f800000u;   // +inf bits
        int      besti = tid * 8;
#pragma unroll
        for (int e = 0; e < 8; e++) {
            m[e] = fminf(m[e], dv[e]);
            float    v = (m[e] < 0.f) ? finf() : m[e];
            unsigned u = __float_as_uint(v);
            if (u < bestv) { bestv = u; besti = tid * 8 + e; }
        }

        // stage 1: warp argmin (value via REDUX, index via ballot/ffs/shfl)
        unsigned wmin = __reduce_min_sync(0xffffffffu, bestv);
        unsigned bal  = __ballot_sync(0xffffffffu, bestv == wmin);
        int      src  = __ffs(bal) - 1;
        int      widx = __shfl_sync(0xffffffffu, besti, src);
        if (lane == 0)
            s_warp[par][wid] = ((unsigned long long)wmin << 32) | (unsigned)widx;
        __syncthreads();

        // stage 2: all warps redundantly reduce the 16 per-warp keys
        unsigned long long k = s_warp[par][lane & 15];
        unsigned kv   = (unsigned)(k >> 32);
        unsigned gmin = __reduce_min_sync(0xffffffffu, kv);
        unsigned bal2 = __ballot_sync(0xffffffffu, kv == gmin);
        int      src2 = __ffs(bal2) - 1;   // lowest lane -> lowest warp -> lowest index
        int      gi   = (int)__shfl_sync(0xffffffffu, (unsigned)k, src2);

        j = gi;
        if ((gi >> 3) == tid) m[gi & 7] = -1.0f;   // owner marks in-tree
        if (tid == 0)
            *(float2*)(out + 2 * step) = make_float2(0.0f, __uint_as_float(gmin));
        par ^= 1;
    }
}

// ---------------------------------------------------------------------------
extern "C" void kernel_launch(void* const* d_in, const int* in_sizes, int n_in,
                              void* d_out, int out_size) {
    const float* x   = (const float*)d_in[0];
    float*       out = (float*)d_out;

    sq_kernel<<<(N + 255) / 256, 256>>>(x);
    dim3 grid(N / 64, N / 64);
    dist_kernel<<<grid, 256>>>(x);
    prim_kernel<<<1, 512>>>(out);
}

// round 6
// speedup vs baseline: 1.4480x; 1.2169x over previous
#include <cuda_runtime.h>
#include <cuda_bf16.h>
#include <cstdint>

#define N 4096
#define DF 64

// Scratch (allocation-free rule: __device__ globals)
__device__ float g_D[(size_t)N * N];   // 64 MB distance matrix, diagonal = +inf
__device__ float g_sq[N];              // squared norms

__device__ __forceinline__ float finf() { return __int_as_float(0x7f800000); }

// ---------------------------------------------------------------------------
// Kernel 0: squared norms
// ---------------------------------------------------------------------------
__global__ void sq_kernel(const float* __restrict__ x) {
    int i = blockIdx.x * blockDim.x + threadIdx.x;
    if (i >= N) return;
    const float4* xi = (const float4*)(x + (size_t)i * DF);
    float s = 0.f;
#pragma unroll
    for (int k = 0; k < DF / 4; k++) {
        float4 v = xi[k];
        s += v.x * v.x + v.y * v.y + v.z * v.z + v.w * v.w;
    }
    g_sq[i] = s;
}

// ---------------------------------------------------------------------------
// Kernel 1: distance matrix, 64x64 tiles, 256 threads, 4x4 per thread.
// ---------------------------------------------------------------------------
__global__ __launch_bounds__(256) void dist_kernel(const float* __restrict__ x) {
    __shared__ __align__(16) float sA[DF * 68];
    __shared__ __align__(16) float sB[DF * 68];

    const int t    = threadIdx.x;
    const int lrow = t >> 2;      // 0..63
    const int q    = t & 3;       // 0..3
    const int i0   = blockIdx.y * 64;
    const int j0   = blockIdx.x * 64;

    {
        const float4* xa = (const float4*)(x + (size_t)(i0 + lrow) * DF) + q * 4;
        const float4* xb = (const float4*)(x + (size_t)(j0 + lrow) * DF) + q * 4;
#pragma unroll
        for (int u = 0; u < 4; u++) {
            float4 va = xa[u];
            float4 vb = xb[u];
            int k0 = q * 16 + u * 4;
            sA[(k0 + 0) * 68 + lrow] = va.x;
            sA[(k0 + 1) * 68 + lrow] = va.y;
            sA[(k0 + 2) * 68 + lrow] = va.z;
            sA[(k0 + 3) * 68 + lrow] = va.w;
            sB[(k0 + 0) * 68 + lrow] = vb.x;
            sB[(k0 + 1) * 68 + lrow] = vb.y;
            sB[(k0 + 2) * 68 + lrow] = vb.z;
            sB[(k0 + 3) * 68 + lrow] = vb.w;
        }
    }
    __syncthreads();

    const int tx = t & 15;
    const int ty = t >> 4;

    float acc[4][4];
#pragma unroll
    for (int r = 0; r < 4; r++)
#pragma unroll
        for (int c = 0; c < 4; c++) acc[r][c] = 0.f;

#pragma unroll 8
    for (int k = 0; k < DF; k++) {
        float4 a = *(const float4*)&sA[k * 68 + ty * 4];
        float4 b = *(const float4*)&sB[k * 68 + tx * 4];
        float av[4] = {a.x, a.y, a.z, a.w};
        float bv[4] = {b.x, b.y, b.z, b.w};
#pragma unroll
        for (int r = 0; r < 4; r++)
#pragma unroll
            for (int c = 0; c < 4; c++) acc[r][c] = fmaf(av[r], bv[c], acc[r][c]);
    }

    float sqI[4], sqJ[4];
#pragma unroll
    for (int r = 0; r < 4; r++) sqI[r] = g_sq[i0 + ty * 4 + r];
#pragma unroll
    for (int c = 0; c < 4; c++) sqJ[c] = g_sq[j0 + tx * 4 + c];

#pragma unroll
    for (int r = 0; r < 4; r++) {
        int gi = i0 + ty * 4 + r;
        float4 o;
        float ov[4];
#pragma unroll
        for (int c = 0; c < 4; c++) {
            int gj = j0 + tx * 4 + c;
            float d2 = sqI[r] + sqJ[c] - 2.f * acc[r][c];
            float d  = sqrtf(fmaxf(d2, 1e-12f));
            ov[c] = (gi == gj) ? finf() : d;
        }
        o.x = ov[0]; o.y = ov[1]; o.z = ov[2]; o.w = ov[3];
        *(float4*)(g_D + (size_t)gi * N + j0 + tx * 4) = o;
    }
}

// ---------------------------------------------------------------------------
// Kernel 2: Prim scan. Single CTA, 256 threads (8 warps), 16 elems/thread
// in registers, fully coalesced loads.
//
// Element mapping: global idx = wid*512 + q*128 + lane*4 + c, local e = q*4+c.
// e ascends <=> global idx ascends within a thread; lane ascends <=> idx
// ascends within (wid,q); wid ascends <=> idx block ascends. So REDUX-min on
// global indices gives exact first-occurrence (jnp.argmin) tiebreak.
//
// Ordering trick: sentinel -1.0f has bits 0xBF800000 which as UNSIGNED is
// greater than +inf bits (0x7F800000). All live distances are positive, so
// unsigned-compare on raw float bits = correct order with in-tree entries
// automatically last. No masking instructions at all.
// ---------------------------------------------------------------------------
__global__ __launch_bounds__(256, 1) void prim_kernel(float* __restrict__ out) {
    __shared__ unsigned long long s_warp[2][8];

    const int tid  = threadIdx.x;
    const int lane = tid & 31;
    const int wid  = tid >> 5;
    const int base = wid * 512 + lane * 4;   // global idx of e=0

    float m[16];
#pragma unroll
    for (int e = 0; e < 16; e++) m[e] = finf();
    if (tid == 0) m[0] = -1.0f;   // vertex 0 starts in the tree

    int j   = 0;
    int par = 0;

    for (int step = 0; step < N - 1; step++) {
        const float4* rp = (const float4*)(g_D + ((size_t)j << 12)) + wid * 128 + lane;
        float4 q0 = __ldcg(rp);
        float4 q1 = __ldcg(rp + 32);
        float4 q2 = __ldcg(rp + 64);
        float4 q3 = __ldcg(rp + 96);
        float dv[16] = {q0.x, q0.y, q0.z, q0.w, q1.x, q1.y, q1.z, q1.w,
                        q2.x, q2.y, q2.z, q2.w, q3.x, q3.y, q3.z, q3.w};

        unsigned v[16];
#pragma unroll
        for (int e = 0; e < 16; e++) {
            m[e] = fminf(m[e], dv[e]);
            v[e] = __float_as_uint(m[e]);   // in-tree (-1.0f) sorts after +inf
        }

        // local argmin: 4-level tree, strict < keeps the earlier (lower) index
        unsigned bv[8]; int be[8];
#pragma unroll
        for (int k = 0; k < 8; k++) {
            bool p = v[2 * k + 1] < v[2 * k];
            bv[k] = p ? v[2 * k + 1] : v[2 * k];
            be[k] = p ? (2 * k + 1) : (2 * k);
        }
#pragma unroll
        for (int k = 0; k < 4; k++) {
            bool p = bv[2 * k + 1] < bv[2 * k];
            bv[k] = p ? bv[2 * k + 1] : bv[2 * k];
            be[k] = p ? be[2 * k + 1] : be[2 * k];
        }
#pragma unroll
        for (int k = 0; k < 2; k++) {
            bool p = bv[2 * k + 1] < bv[2 * k];
            bv[k] = p ? bv[2 * k + 1] : bv[2 * k];
            be[k] = p ? be[2 * k + 1] : be[2 * k];
        }
        bool p0 = bv[1] < bv[0];
        unsigned myv = p0 ? bv[1] : bv[0];
        int      e0  = p0 ? be[1] : be[0];
        int besti = base + ((e0 >> 2) << 7) + (e0 & 3);

        // stage 1: warp argmin via two REDUX ops (value, then index)
        unsigned wmin = __reduce_min_sync(0xffffffffu, myv);
        unsigned cand = (myv == wmin) ? (unsigned)besti : 0xffffffffu;
        unsigned widx = __reduce_min_sync(0xffffffffu, cand);
        if (lane == 0)
            s_warp[par][wid] = ((unsigned long long)wmin << 32) | widx;
        __syncthreads();

        // stage 2: every warp redundantly reduces the 8 per-warp keys
        unsigned long long k8 =
            (lane < 8) ? s_warp[par][lane] : 0xffffffffffffffffull;
        unsigned kv   = (unsigned)(k8 >> 32);
        unsigned gmin = __reduce_min_sync(0xffffffffu, kv);
        unsigned c2   = (kv == gmin) ? (unsigned)k8 : 0xffffffffu;
        unsigned gi   = __reduce_min_sync(0xffffffffu, c2);

        j = (int)gi;
        int own = (int)(((gi >> 9) << 5) | ((gi >> 2) & 31));
        if (own == tid) {
            int e = (((gi >> 7) & 3) << 2) | (gi & 3);
            m[e] = -1.0f;   // join tree
        }
        if (tid == 0)
            *(float2*)(out + 2 * step) = make_float2(0.0f, __uint_as_float(gmin));
        par ^= 1;
    }
}

// ---------------------------------------------------------------------------
extern "C" void kernel_launch(void* const* d_in, const int* in_sizes, int n_in,
                              void* d_out, int out_size) {
    const float* x   = (const float*)d_in[0];
    float*       out = (float*)d_out;

    sq_kernel<<<(N + 255) / 256, 256>>>(x);
    dim3 grid(N / 64, N / 64);
    dist_kernel<<<grid, 256>>>(x);
    prim_kernel<<<1, 256>>>(out);
}